// round 14
// baseline (speedup 1.0000x reference)
#include <cuda_runtime.h>
#include <cuda_fp16.h>
#include <math.h>
#include <stdint.h>

#define DIM    1024
#define BATCH  2
#define NSEQ   2048
#define HEADS  16
#define HD     64
#define TOKENS (BATCH * NSEQ)     // 4096
#define C3     (3 * DIM)          // 3072
#define QSCALE 0.1803368801111204f   // 0.125 * log2(e)

// ---------------- scratch -----------------------------------------------
__device__ __half g_ln[TOKENS * DIM];
__device__ __half g_wqkvT[C3 * DIM];    // [N=3072][K=1024]
__device__ __half g_wprojT[DIM * DIM];  // [N=1024][K=1024]
__device__ __half g_q[BATCH * HEADS * NSEQ * HD];   // [bh][n][64], pre-scaled
__device__ __half g_k[BATCH * HEADS * NSEQ * HD];
__device__ __half g_v[BATCH * HEADS * NSEQ * HD];
__device__ __half g_attn[TOKENS * DIM];

// ---------------- helpers ------------------------------------------------
__device__ __forceinline__ uint32_t smem_u32(const void* p) {
    uint32_t a;
    asm("{ .reg .u64 t; cvta.to.shared.u64 t, %1; cvt.u32.u64 %0, t; }"
        : "=r"(a) : "l"(p));
    return a;
}
__device__ __forceinline__ uint32_t sw(uint32_t o) {   // SW128 XOR swizzle
    return o ^ ((o >> 3) & 0x70);
}
__device__ __forceinline__ void ldsm4(uint32_t* r, uint32_t a) {
    asm volatile("ldmatrix.sync.aligned.m8n8.x4.shared.b16 {%0,%1,%2,%3}, [%4];"
                 : "=r"(r[0]), "=r"(r[1]), "=r"(r[2]), "=r"(r[3]) : "r"(a));
}
__device__ __forceinline__ void ldsm4t(uint32_t* r, uint32_t a) {
    asm volatile("ldmatrix.sync.aligned.m8n8.x4.trans.shared.b16 {%0,%1,%2,%3}, [%4];"
                 : "=r"(r[0]), "=r"(r[1]), "=r"(r[2]), "=r"(r[3]) : "r"(a));
}
// fp16-acc MMA
__device__ __forceinline__ void mma16816h(uint32_t* c, const uint32_t* a,
                                          uint32_t b0, uint32_t b1) {
    asm volatile(
        "mma.sync.aligned.m16n8k16.row.col.f16.f16.f16.f16 "
        "{%0,%1}, {%2,%3,%4,%5}, {%6,%7}, {%0,%1};"
        : "+r"(c[0]), "+r"(c[1])
        : "r"(a[0]), "r"(a[1]), "r"(a[2]), "r"(a[3]), "r"(b0), "r"(b1));
}
#define CP16(dst, src) \
    asm volatile("cp.async.cg.shared.global [%0], [%1], 16;" :: "r"(dst), "l"(src))
#define CP_COMMIT() asm volatile("cp.async.commit_group;" ::: "memory")
#define CP_WAIT1()  asm volatile("cp.async.wait_group 1;" ::: "memory")
#define CP_WAIT0()  asm volatile("cp.async.wait_group 0;" ::: "memory")

__device__ __forceinline__ uint32_t hex2(uint32_t x) {   // 2^x on fp16x2
    uint32_t y;
    asm("ex2.approx.f16x2 %0, %1;" : "=r"(y) : "r"(x));
    return y;
}
__device__ __forceinline__ uint32_t pack_f16(float lo, float hi) {
    uint32_t r;
    asm("cvt.rn.f16x2.f32 %0, %1, %2;" : "=r"(r) : "f"(hi), "f"(lo));
    return r;
}

// ---------------------------------------------------------------------------
// Merged pre-pass: one launch does LN (blocks 0..4095), wqkv transpose
// (4096..7167), wproj transpose (7168..8191). All 256-thread blocks.
// ---------------------------------------------------------------------------
__device__ __forceinline__ void do_transpose(
    const float* __restrict__ W, __half* __restrict__ T,
    int K, int N, int n0, int k0, int tid) {
    __shared__ float tile[32][33];
    int tx = tid & 31, ty = tid >> 5;
    #pragma unroll
    for (int r = ty; r < 32; r += 8)
        tile[r][tx] = W[(size_t)(k0 + r) * N + n0 + tx];
    __syncthreads();
    #pragma unroll
    for (int r = ty; r < 32; r += 8)
        T[(size_t)(n0 + r) * K + k0 + tx] = __float2half(tile[tx][r]);
}

__global__ __launch_bounds__(256) void prepass_kernel(
    const float* __restrict__ x, const float* __restrict__ gamma,
    const float* __restrict__ beta, const float* __restrict__ w_qkv,
    const float* __restrict__ w_proj) {
    int bx = blockIdx.x;
    int t = threadIdx.x;

    if (bx < TOKENS) {
        // ---- LayerNorm row ----
        int row = bx;
        const float4* xr = (const float4*)(x + (size_t)row * DIM);
        float4 v = xr[t];

        float s  = v.x + v.y + v.z + v.w;
        float ss = v.x*v.x + v.y*v.y + v.z*v.z + v.w*v.w;
        #pragma unroll
        for (int o = 16; o > 0; o >>= 1) {
            s  += __shfl_xor_sync(0xFFFFFFFFu, s,  o);
            ss += __shfl_xor_sync(0xFFFFFFFFu, ss, o);
        }
        __shared__ float rs[8], rss[8];
        int w = t >> 5;
        if ((t & 31) == 0) { rs[w] = s; rss[w] = ss; }
        __syncthreads();
        s = 0.f; ss = 0.f;
        #pragma unroll
        for (int i = 0; i < 8; i++) { s += rs[i]; ss += rss[i]; }

        const float invD = 1.0f / DIM;
        float mean = s * invD;
        float var  = ss * invD - mean * mean;
        float rstd = rsqrtf(var + 1e-5f);

        float4 g  = ((const float4*)gamma)[t];
        float4 be = ((const float4*)beta)[t];
        float o0 = (v.x - mean) * rstd * g.x + be.x;
        float o1 = (v.y - mean) * rstd * g.y + be.y;
        float o2 = (v.z - mean) * rstd * g.z + be.z;
        float o3 = (v.w - mean) * rstd * g.w + be.w;

        size_t idx = (size_t)row * DIM + t * 4;
        *(uint32_t*)(g_ln + idx)     = pack_f16(o0, o1);
        *(uint32_t*)(g_ln + idx + 2) = pack_f16(o2, o3);
    } else if (bx < TOKENS + (C3 / 32) * (DIM / 32)) {
        // ---- w_qkv transpose tile ----
        int id = bx - TOKENS;
        int n0 = (id % (C3 / 32)) * 32;
        int k0 = (id / (C3 / 32)) * 32;
        do_transpose(w_qkv, g_wqkvT, DIM, C3, n0, k0, t);
    } else {
        // ---- w_proj transpose tile ----
        int id = bx - TOKENS - (C3 / 32) * (DIM / 32);
        int n0 = (id % (DIM / 32)) * 32;
        int k0 = (id / (DIM / 32)) * 32;
        do_transpose(w_proj, g_wprojT, DIM, DIM, n0, k0, t);
    }
}
#define PREPASS_BLOCKS (TOKENS + (C3 / 32) * (DIM / 32) + (DIM / 32) * (DIM / 32))

// ---------------------------------------------------------------------------
// QKV GEMM: CTA 128x256, 4 warps (2Mx2N, warp 64x128), K-chunk 64, 2-stage.
// Spill-proof inner loop: A frags hoisted (16 regs), single B frag live.
// Stage 48KB: A@0 (16KB), B@16384 (32KB). 2 CTAs/SM (smem-bound).
// ---------------------------------------------------------------------------
#define QSTAGE 49152
#define QSMEM  (2 * QSTAGE)
#define NCH    (DIM / 64)   // 16

__device__ __forceinline__ void qkv_load_stage(
    const __half* A, const __half* B, int crow, int ccol, int ch,
    uint32_t sbase, int tid) {
    #pragma unroll
    for (int j = 0; j < 8; j++) {             // A: 128 rows
        int i = tid + j * 128;
        int row = i >> 3, c16 = i & 7;
        uint32_t d = sbase + sw((uint32_t)(row * 128 + c16 * 16));
        CP16(d, A + (size_t)(crow + row) * DIM + ch * 64 + c16 * 8);
    }
    #pragma unroll
    for (int j = 0; j < 16; j++) {            // B: 256 rows
        int i = tid + j * 128;
        int row = i >> 3, c16 = i & 7;
        uint32_t d = sbase + 16384 + sw((uint32_t)(row * 128 + c16 * 16));
        CP16(d, B + (size_t)(ccol + row) * DIM + ch * 64 + c16 * 8);
    }
}

__global__ __launch_bounds__(128, 2) void gemm_qkv(
    const __half* __restrict__ A, const __half* __restrict__ B) {

    extern __shared__ char smc[];
    uint32_t smb = smem_u32(smc);
    int tid = threadIdx.x, wid = tid >> 5, lane = tid & 31;
    int wm = wid & 1, wn = wid >> 1;
    int crow = blockIdx.y * 128, ccol = blockIdx.x * 256;

    uint32_t acc[4][16][2];   // 64x128 warp tile, fp16x2 accumulators (128 regs)
    #pragma unroll
    for (int a = 0; a < 4; a++)
        #pragma unroll
        for (int b = 0; b < 16; b++) { acc[a][b][0] = 0u; acc[a][b][1] = 0u; }

    qkv_load_stage(A, B, crow, ccol, 0, smb, tid);
    CP_COMMIT();

    for (int ch = 0; ch < NCH; ch++) {
        CP_WAIT0();
        __syncthreads();
        if (ch + 1 < NCH) {
            qkv_load_stage(A, B, crow, ccol, ch + 1,
                           smb + ((ch + 1) & 1) * QSTAGE, tid);
            CP_COMMIT();
        }

        uint32_t Abase = smb + (ch & 1) * QSTAGE;
        uint32_t Bbase = Abase + 16384;

        #pragma unroll
        for (int kt = 0; kt < 4; kt++) {
            // hoist A fragments (4 x 4 = 16 regs)
            uint32_t af[4][4];
            #pragma unroll
            for (int mt = 0; mt < 4; mt++) {
                uint32_t aoff = Abase + sw((uint32_t)(
                    (wm * 64 + mt * 16 + (lane & 15)) * 128 +
                    kt * 32 + (lane >> 4) * 16));
                ldsm4(af[mt], aoff);
            }
            // stream B fragments one at a time; 8 MMAs per B-load
            #pragma unroll
            for (int jp = 0; jp < 8; jp++) {
                uint32_t bf[4];
                uint32_t boff = Bbase + sw((uint32_t)(
                    (wn * 128 + jp * 16 + (lane >> 4) * 8 + (lane & 7)) * 128 +
                    kt * 32 + ((lane >> 3) & 1) * 16));
                ldsm4(bf, boff);
                #pragma unroll
                for (int mt = 0; mt < 4; mt++) {
                    mma16816h(acc[mt][2*jp],   af[mt], bf[0], bf[1]);
                    mma16816h(acc[mt][2*jp+1], af[mt], bf[2], bf[3]);
                }
            }
        }
    }

    // epilogue: scatter to q/k/v
    int g = lane >> 2, t2 = (lane & 3) * 2;
    const __half2 qsc = __float2half2_rn(QSCALE);
    #pragma unroll
    for (int mt = 0; mt < 4; mt++) {
        int row0 = crow + wm * 64 + mt * 16 + g;
        #pragma unroll
        for (int j = 0; j < 16; j++) {
            int col = ccol + wn * 128 + j * 8 + t2;
            int which = col >> 10, rem = col & 1023;
            int h = rem >> 6, d = rem & 63;
            __half* dst = (which == 0) ? g_q : (which == 1) ? g_k : g_v;
            #pragma unroll
            for (int r = 0; r < 2; r++) {
                int tok = row0 + r * 8;
                __half2 hv = *(__half2*)&acc[mt][j][r];
                if (which == 0) hv = __hmul2(hv, qsc);
                size_t off = ((size_t)((tok >> 11) * HEADS + h) * NSEQ +
                              (tok & (NSEQ - 1))) * HD + d;
                *(__half2*)(dst + off) = hv;
            }
        }
    }
}

// ---------------------------------------------------------------------------
// Proj GEMM (round-9 winner): CTA 128x128, 4 warps, K-chunk 64, 2-stage,
// 3 CTAs/SM, +bias +residual, fp32 out.
// ---------------------------------------------------------------------------
#define GSTAGE 32768
#define GSMEM  (2 * GSTAGE)

__device__ __forceinline__ void gemm_load_stage(
    const __half* A, const __half* B, int crow, int ccol, int ch,
    uint32_t sbase, int tid) {
    #pragma unroll
    for (int j = 0; j < 8; j++) {
        int i = tid + j * 128;
        int row = i >> 3, c16 = i & 7;
        uint32_t d = sbase + sw((uint32_t)(row * 128 + c16 * 16));
        size_t off = (size_t)row * DIM + ch * 64 + c16 * 8;
        CP16(d,         A + (size_t)crow * DIM + off);
        CP16(d + 16384, B + (size_t)ccol * DIM + off);
    }
}

__global__ __launch_bounds__(128, 3) void gemm_proj(
    const __half* __restrict__ A, const __half* __restrict__ B,
    float* __restrict__ out, const float* __restrict__ bias,
    const float* __restrict__ resid) {

    extern __shared__ char smc[];
    uint32_t smb = smem_u32(smc);
    int tid = threadIdx.x, wid = tid >> 5, lane = tid & 31;
    int wm = wid & 1, wn = wid >> 1;
    int crow = blockIdx.y * 128, ccol = blockIdx.x * 128;

    uint32_t acc[4][8][2];
    #pragma unroll
    for (int a = 0; a < 4; a++)
        #pragma unroll
        for (int b = 0; b < 8; b++) { acc[a][b][0] = 0u; acc[a][b][1] = 0u; }

    gemm_load_stage(A, B, crow, ccol, 0, smb, tid);
    CP_COMMIT();

    for (int ch = 0; ch < NCH; ch++) {
        CP_WAIT0();
        __syncthreads();
        if (ch + 1 < NCH) {
            gemm_load_stage(A, B, crow, ccol, ch + 1,
                            smb + ((ch + 1) & 1) * GSTAGE, tid);
            CP_COMMIT();
        }

        uint32_t Abase = smb + (ch & 1) * GSTAGE;
        uint32_t Bbase = Abase + 16384;

        #pragma unroll
        for (int kt = 0; kt < 4; kt++) {
            uint32_t bf[4][4];
            #pragma unroll
            for (int jp = 0; jp < 4; jp++) {
                uint32_t boff = Bbase + sw((uint32_t)(
                    (wn * 64 + jp * 16 + (lane >> 4) * 8 + (lane & 7)) * 128 +
                    kt * 32 + ((lane >> 3) & 1) * 16));
                ldsm4(bf[jp], boff);
            }
            #pragma unroll
            for (int mt = 0; mt < 4; mt++) {
                uint32_t af[4];
                uint32_t aoff = Abase + sw((uint32_t)(
                    (wm * 64 + mt * 16 + (lane & 15)) * 128 +
                    kt * 32 + (lane >> 4) * 16));
                ldsm4(af, aoff);
                #pragma unroll
                for (int jp = 0; jp < 4; jp++) {
                    mma16816h(acc[mt][2*jp],   af, bf[jp][0], bf[jp][1]);
                    mma16816h(acc[mt][2*jp+1], af, bf[jp][2], bf[jp][3]);
                }
            }
        }
    }

    int g = lane >> 2, t2 = (lane & 3) * 2;
    #pragma unroll
    for (int mt = 0; mt < 4; mt++) {
        int row0 = crow + wm * 64 + mt * 16 + g;
        #pragma unroll
        for (int j = 0; j < 8; j++) {
            int col = ccol + wn * 64 + j * 8 + t2;
            float b0 = bias[col], b1 = bias[col + 1];
            #pragma unroll
            for (int r = 0; r < 2; r++) {
                size_t o = (size_t)(row0 + r * 8) * DIM + col;
                float2 rr = *(const float2*)(resid + o);
                float2 f = __half22float2(*(__half2*)&acc[mt][j][r]);
                float2 vv = { f.x + b0 + rr.x, f.y + b1 + rr.y };
                *(float2*)(out + o) = vv;
            }
        }
    }
}

// ---------------------------------------------------------------------------
// Flash attention, max-free (round-13 winner): CTA = 256 q x one (b,h),
// 4 warps x 64 q, full fp16 acc, P in place. 2 CTAs/SM.
// ---------------------------------------------------------------------------
#define ASTAGE 16384
#define ASMEM  (32768 + 3 * ASTAGE)
#define NT     (NSEQ / 64)   // 32

__device__ __forceinline__ void kv_load_stage(
    const __half* kg, const __half* vg, int k0, uint32_t sbase, int tid) {
    #pragma unroll
    for (int j = 0; j < 4; j++) {
        int i = tid + j * 128;
        int key = i >> 3, ck = i & 7;
        uint32_t d = sbase + sw((uint32_t)(key * 128 + ck * 16));
        size_t gsrc = (size_t)(k0 + key) * HD + ck * 8;
        CP16(d,        kg + gsrc);
        CP16(d + 8192, vg + gsrc);
    }
}

__global__ __launch_bounds__(128, 2) void attn_mma() {
    extern __shared__ char smc[];
    uint32_t smb = smem_u32(smc);
    int tid = threadIdx.x, wid = tid >> 5, lane = tid & 31;
    int bh = blockIdx.y;
    int q0 = blockIdx.x * 256;

    const __half* qg = g_q + (size_t)bh * NSEQ * HD;
    const __half* kg = g_k + (size_t)bh * NSEQ * HD;
    const __half* vg = g_v + (size_t)bh * NSEQ * HD;

    kv_load_stage(kg, vg, 0, smb + 32768, tid);
    CP_COMMIT();
    kv_load_stage(kg, vg, 64, smb + 32768 + ASTAGE, tid);
    CP_COMMIT();

    #pragma unroll
    for (int it = 0; it < 16; it++) {
        int i = tid + it * 128;
        int row = i >> 3, ck = i & 7;
        uint4 val = *(const uint4*)(qg + (size_t)(q0 + row) * HD + ck * 8);
        *(uint4*)(smc + sw((uint32_t)(row * 128 + ck * 16))) = val;
    }
    __syncthreads();

    uint32_t qa[4][4][4];
    #pragma unroll
    for (int mt = 0; mt < 4; mt++)
        #pragma unroll
        for (int kt = 0; kt < 4; kt++) {
            uint32_t off = smb + sw((uint32_t)(
                (wid * 64 + mt * 16 + (lane & 15)) * 128 +
                kt * 32 + (lane >> 4) * 16));
            ldsm4(qa[mt][kt], off);
        }

    uint32_t oh[4][8][2];
    #pragma unroll
    for (int mt = 0; mt < 4; mt++)
        #pragma unroll
        for (int j = 0; j < 8; j++) { oh[mt][j][0] = 0u; oh[mt][j][1] = 0u; }
    float l[4][2];
    #pragma unroll
    for (int mt = 0; mt < 4; mt++) { l[mt][0] = 0.f; l[mt][1] = 0.f; }

    for (int t = 0; t < NT; t++) {
        if (t + 2 < NT) CP_WAIT1(); else CP_WAIT0();
        __syncthreads();
        if (t + 2 < NT) {
            kv_load_stage(kg, vg, (t + 2) * 64,
                          smb + 32768 + ((t + 2) % 3) * ASTAGE, tid);
            CP_COMMIT();
        }

        uint32_t Kb = smb + 32768 + (t % 3) * ASTAGE;
        uint32_t Vb = Kb + 8192;

        uint32_t sc[4][8][2];
        #pragma unroll
        for (int mt = 0; mt < 4; mt++)
            #pragma unroll
            for (int j = 0; j < 8; j++) { sc[mt][j][0] = 0u; sc[mt][j][1] = 0u; }

        #pragma unroll
        for (int kt = 0; kt < 4; kt++) {
            uint32_t kf[4][4];
            #pragma unroll
            for (int jp = 0; jp < 4; jp++) {
                uint32_t off = Kb + sw((uint32_t)(
                    (jp * 16 + (lane >> 4) * 8 + (lane & 7)) * 128 +
                    kt * 32 + ((lane >> 3) & 1) * 16));
                ldsm4(kf[jp], off);
            }
            #pragma unroll
            for (int mt = 0; mt < 4; mt++)
                #pragma unroll
                for (int jp = 0; jp < 4; jp++) {
                    mma16816h(sc[mt][2*jp],   qa[mt][kt], kf[jp][0], kf[jp][1]);
                    mma16816h(sc[mt][2*jp+1], qa[mt][kt], kf[jp][2], kf[jp][3]);
                }
        }

        #pragma unroll
        for (int mt = 0; mt < 4; mt++) {
            __half2 ls0 = __float2half2_rn(0.f), ls1 = __float2half2_rn(0.f);
            #pragma unroll
            for (int j = 0; j < 8; j++) {
                sc[mt][j][0] = hex2(sc[mt][j][0]);
                sc[mt][j][1] = hex2(sc[mt][j][1]);
                ls0 = __hadd2(ls0, *(__half2*)&sc[mt][j][0]);
                ls1 = __hadd2(ls1, *(__half2*)&sc[mt][j][1]);
            }
            l[mt][0] += __low2float(ls0) + __high2float(ls0);
            l[mt][1] += __low2float(ls1) + __high2float(ls1);
        }

        #pragma unroll
        for (int kt = 0; kt < 4; kt++) {
            uint32_t vf[4][4];
            #pragma unroll
            for (int j2 = 0; j2 < 4; j2++) {
                uint32_t off = Vb + sw((uint32_t)(
                    (kt * 16 + ((lane >> 3) & 1) * 8 + (lane & 7)) * 128 +
                    j2 * 32 + ((lane >> 4) & 1) * 16));
                ldsm4t(vf[j2], off);
            }
            #pragma unroll
            for (int mt = 0; mt < 4; mt++)
                #pragma unroll
                for (int j2 = 0; j2 < 4; j2++) {
                    mma16816h(oh[mt][2*j2],   &sc[mt][2*kt][0], vf[j2][0], vf[j2][1]);
                    mma16816h(oh[mt][2*j2+1], &sc[mt][2*kt][0], vf[j2][2], vf[j2][3]);
                }
        }
    }

    int b = bh >> 4, h = bh & 15;
    #pragma unroll
    for (int mt = 0; mt < 4; mt++) {
        float l0 = l[mt][0], l1 = l[mt][1];
        l0 += __shfl_xor_sync(0xFFFFFFFFu, l0, 1);
        l0 += __shfl_xor_sync(0xFFFFFFFFu, l0, 2);
        l1 += __shfl_xor_sync(0xFFFFFFFFu, l1, 1);
        l1 += __shfl_xor_sync(0xFFFFFFFFu, l1, 2);
        float inv0 = 1.f / l0, inv1 = 1.f / l1;

        int n0 = q0 + wid * 64 + mt * 16 + (lane >> 2);
        size_t t0 = (size_t)(b * NSEQ + n0) * DIM + h * HD;
        size_t t1 = t0 + (size_t)8 * DIM;
        #pragma unroll
        for (int j = 0; j < 8; j++) {
            int d = j * 8 + (lane & 3) * 2;
            float2 f0 = __half22float2(*(__half2*)&oh[mt][j][0]);
            float2 f1 = __half22float2(*(__half2*)&oh[mt][j][1]);
            *(uint32_t*)(g_attn + t0 + d) = pack_f16(f0.x * inv0, f0.y * inv0);
            *(uint32_t*)(g_attn + t1 + d) = pack_f16(f1.x * inv1, f1.y * inv1);
        }
    }
}

// ---------------------------------------------------------------------------
extern "C" void kernel_launch(void* const* d_in, const int* in_sizes, int n_in,
                              void* d_out, int out_size) {
    const float* x      = (const float*)d_in[0];
    const float* w_qkv  = (const float*)d_in[1];
    const float* w_proj = (const float*)d_in[2];
    const float* b_proj = (const float*)d_in[3];
    const float* gamma  = (const float*)d_in[4];
    const float* beta   = (const float*)d_in[5];
    float* out = (float*)d_out;

    cudaFuncSetAttribute(gemm_qkv,  cudaFuncAttributeMaxDynamicSharedMemorySize, QSMEM);
    cudaFuncSetAttribute(gemm_proj, cudaFuncAttributeMaxDynamicSharedMemorySize, GSMEM);
    cudaFuncSetAttribute(attn_mma,  cudaFuncAttributeMaxDynamicSharedMemorySize, ASMEM);

    __half *lnp, *wqp, *wpp, *atp;
    cudaGetSymbolAddress((void**)&lnp, g_ln);
    cudaGetSymbolAddress((void**)&wqp, g_wqkvT);
    cudaGetSymbolAddress((void**)&wpp, g_wprojT);
    cudaGetSymbolAddress((void**)&atp, g_attn);

    // 1. merged pre-pass: LN + both weight transposes
    prepass_kernel<<<PREPASS_BLOCKS, 256>>>(x, gamma, beta, w_qkv, w_proj);

    // 2. QKV GEMM (128x256 tiles, spill-proof) -> scatter fp16 q/k/v
    gemm_qkv<<<dim3(C3 / 256, TOKENS / 128), 128, QSMEM>>>(lnp, wqp);

    // 3. attention (256-q CTAs) -> fp16 [token][1024]
    attn_mma<<<dim3(NSEQ / 256, BATCH * HEADS), 128, ASMEM>>>();

    // 4. proj GEMM + bias + residual -> d_out
    gemm_proj<<<dim3(DIM / 128, TOKENS / 128), 128, GSMEM>>>(
        atp, wpp, out, b_proj, x);
}

// round 15
// speedup vs baseline: 1.0549x; 1.0549x over previous
#include <cuda_runtime.h>
#include <cuda_fp16.h>
#include <math.h>
#include <stdint.h>

#define DIM    1024
#define BATCH  2
#define NSEQ   2048
#define HEADS  16
#define HD     64
#define TOKENS (BATCH * NSEQ)     // 4096
#define C3     (3 * DIM)          // 3072
#define QSCALE 0.1803368801111204f   // 0.125 * log2(e)

// ---------------- scratch -----------------------------------------------
__device__ __half g_ln[TOKENS * DIM];
__device__ __half g_wqkvT[C3 * DIM];    // [N=3072][K=1024]
__device__ __half g_wprojT[DIM * DIM];  // [N=1024][K=1024]
__device__ __half g_q[BATCH * HEADS * NSEQ * HD];   // [bh][n][64], pre-scaled
__device__ __half g_k[BATCH * HEADS * NSEQ * HD];
__device__ __half g_v[BATCH * HEADS * NSEQ * HD];
__device__ __half g_attn[TOKENS * DIM];

// ---------------- helpers ------------------------------------------------
__device__ __forceinline__ uint32_t smem_u32(const void* p) {
    uint32_t a;
    asm("{ .reg .u64 t; cvta.to.shared.u64 t, %1; cvt.u32.u64 %0, t; }"
        : "=r"(a) : "l"(p));
    return a;
}
__device__ __forceinline__ uint32_t sw(uint32_t o) {   // SW128 XOR swizzle
    return o ^ ((o >> 3) & 0x70);
}
__device__ __forceinline__ void ldsm4(uint32_t* r, uint32_t a) {
    asm volatile("ldmatrix.sync.aligned.m8n8.x4.shared.b16 {%0,%1,%2,%3}, [%4];"
                 : "=r"(r[0]), "=r"(r[1]), "=r"(r[2]), "=r"(r[3]) : "r"(a));
}
__device__ __forceinline__ void ldsm4t(uint32_t* r, uint32_t a) {
    asm volatile("ldmatrix.sync.aligned.m8n8.x4.trans.shared.b16 {%0,%1,%2,%3}, [%4];"
                 : "=r"(r[0]), "=r"(r[1]), "=r"(r[2]), "=r"(r[3]) : "r"(a));
}
// fp16-acc MMA
__device__ __forceinline__ void mma16816h(uint32_t* c, const uint32_t* a,
                                          uint32_t b0, uint32_t b1) {
    asm volatile(
        "mma.sync.aligned.m16n8k16.row.col.f16.f16.f16.f16 "
        "{%0,%1}, {%2,%3,%4,%5}, {%6,%7}, {%0,%1};"
        : "+r"(c[0]), "+r"(c[1])
        : "r"(a[0]), "r"(a[1]), "r"(a[2]), "r"(a[3]), "r"(b0), "r"(b1));
}
#define CP16(dst, src) \
    asm volatile("cp.async.cg.shared.global [%0], [%1], 16;" :: "r"(dst), "l"(src))
#define CP_COMMIT() asm volatile("cp.async.commit_group;" ::: "memory")
#define CP_WAIT1()  asm volatile("cp.async.wait_group 1;" ::: "memory")
#define CP_WAIT0()  asm volatile("cp.async.wait_group 0;" ::: "memory")

__device__ __forceinline__ uint32_t hex2(uint32_t x) {   // 2^x on fp16x2
    uint32_t y;
    asm("ex2.approx.f16x2 %0, %1;" : "=r"(y) : "r"(x));
    return y;
}
__device__ __forceinline__ uint32_t pack_f16(float lo, float hi) {
    uint32_t r;
    asm("cvt.rn.f16x2.f32 %0, %1, %2;" : "=r"(r) : "f"(hi), "f"(lo));
    return r;
}

// ---------------------------------------------------------------------------
// Merged pre-pass: LN rows (blocks 0..4095) + wqkv transpose + wproj transpose.
// ---------------------------------------------------------------------------
__device__ __forceinline__ void do_transpose(
    const float* __restrict__ W, __half* __restrict__ T,
    int K, int N, int n0, int k0, int tid) {
    __shared__ float tile[32][33];
    int tx = tid & 31, ty = tid >> 5;
    #pragma unroll
    for (int r = ty; r < 32; r += 8)
        tile[r][tx] = W[(size_t)(k0 + r) * N + n0 + tx];
    __syncthreads();
    #pragma unroll
    for (int r = ty; r < 32; r += 8)
        T[(size_t)(n0 + r) * K + k0 + tx] = __float2half(tile[tx][r]);
}

__global__ __launch_bounds__(256) void prepass_kernel(
    const float* __restrict__ x, const float* __restrict__ gamma,
    const float* __restrict__ beta, const float* __restrict__ w_qkv,
    const float* __restrict__ w_proj) {
    int bx = blockIdx.x;
    int t = threadIdx.x;

    if (bx < TOKENS) {
        int row = bx;
        const float4* xr = (const float4*)(x + (size_t)row * DIM);
        float4 v = xr[t];

        float s  = v.x + v.y + v.z + v.w;
        float ss = v.x*v.x + v.y*v.y + v.z*v.z + v.w*v.w;
        #pragma unroll
        for (int o = 16; o > 0; o >>= 1) {
            s  += __shfl_xor_sync(0xFFFFFFFFu, s,  o);
            ss += __shfl_xor_sync(0xFFFFFFFFu, ss, o);
        }
        __shared__ float rs[8], rss[8];
        int w = t >> 5;
        if ((t & 31) == 0) { rs[w] = s; rss[w] = ss; }
        __syncthreads();
        s = 0.f; ss = 0.f;
        #pragma unroll
        for (int i = 0; i < 8; i++) { s += rs[i]; ss += rss[i]; }

        const float invD = 1.0f / DIM;
        float mean = s * invD;
        float var  = ss * invD - mean * mean;
        float rstd = rsqrtf(var + 1e-5f);

        float4 g  = ((const float4*)gamma)[t];
        float4 be = ((const float4*)beta)[t];
        float o0 = (v.x - mean) * rstd * g.x + be.x;
        float o1 = (v.y - mean) * rstd * g.y + be.y;
        float o2 = (v.z - mean) * rstd * g.z + be.z;
        float o3 = (v.w - mean) * rstd * g.w + be.w;

        size_t idx = (size_t)row * DIM + t * 4;
        *(uint32_t*)(g_ln + idx)     = pack_f16(o0, o1);
        *(uint32_t*)(g_ln + idx + 2) = pack_f16(o2, o3);
    } else if (bx < TOKENS + (C3 / 32) * (DIM / 32)) {
        int id = bx - TOKENS;
        int n0 = (id % (C3 / 32)) * 32;
        int k0 = (id / (C3 / 32)) * 32;
        do_transpose(w_qkv, g_wqkvT, DIM, C3, n0, k0, t);
    } else {
        int id = bx - TOKENS - (C3 / 32) * (DIM / 32);
        int n0 = (id % (DIM / 32)) * 32;
        int k0 = (id / (DIM / 32)) * 32;
        do_transpose(w_proj, g_wprojT, DIM, DIM, n0, k0, t);
    }
}
#define PREPASS_BLOCKS (TOKENS + (C3 / 32) * (DIM / 32) + (DIM / 32) * (DIM / 32))

// ---------------------------------------------------------------------------
// QKV GEMM (round-13 winner): CTA 128x128, 4 warps (2x2, warp 64x64),
// K-chunk 64, 2-stage cp.async, 3 CTAs/SM. Scatter epilogue.
// ---------------------------------------------------------------------------
#define GSTAGE 32768
#define GSMEM  (2 * GSTAGE)
#define NCH    (DIM / 64)   // 16

__device__ __forceinline__ void gemm_load_stage(
    const __half* A, const __half* B, int crow, int ccol, int ch,
    uint32_t sbase, int tid) {
    #pragma unroll
    for (int j = 0; j < 8; j++) {
        int i = tid + j * 128;
        int row = i >> 3, c16 = i & 7;
        uint32_t d = sbase + sw((uint32_t)(row * 128 + c16 * 16));
        size_t off = (size_t)row * DIM + ch * 64 + c16 * 8;
        CP16(d,         A + (size_t)crow * DIM + off);
        CP16(d + 16384, B + (size_t)ccol * DIM + off);
    }
}

__global__ __launch_bounds__(128, 3) void gemm_qkv(
    const __half* __restrict__ A, const __half* __restrict__ B) {

    extern __shared__ char smc[];
    uint32_t smb = smem_u32(smc);
    int tid = threadIdx.x, wid = tid >> 5, lane = tid & 31;
    int wm = wid & 1, wn = wid >> 1;
    int crow = blockIdx.y * 128, ccol = blockIdx.x * 128;

    uint32_t acc[4][8][2];
    #pragma unroll
    for (int a = 0; a < 4; a++)
        #pragma unroll
        for (int b = 0; b < 8; b++) { acc[a][b][0] = 0u; acc[a][b][1] = 0u; }

    gemm_load_stage(A, B, crow, ccol, 0, smb, tid);
    CP_COMMIT();

    for (int ch = 0; ch < NCH; ch++) {
        CP_WAIT0();
        __syncthreads();
        if (ch + 1 < NCH) {
            gemm_load_stage(A, B, crow, ccol, ch + 1,
                            smb + ((ch + 1) & 1) * GSTAGE, tid);
            CP_COMMIT();
        }

        uint32_t Abase = smb + (ch & 1) * GSTAGE;
        uint32_t Bbase = Abase + 16384;

        #pragma unroll
        for (int kt = 0; kt < 4; kt++) {
            uint32_t bf[4][4];
            #pragma unroll
            for (int jp = 0; jp < 4; jp++) {
                uint32_t boff = Bbase + sw((uint32_t)(
                    (wn * 64 + jp * 16 + (lane >> 4) * 8 + (lane & 7)) * 128 +
                    kt * 32 + ((lane >> 3) & 1) * 16));
                ldsm4(bf[jp], boff);
            }
            #pragma unroll
            for (int mt = 0; mt < 4; mt++) {
                uint32_t af[4];
                uint32_t aoff = Abase + sw((uint32_t)(
                    (wm * 64 + mt * 16 + (lane & 15)) * 128 +
                    kt * 32 + (lane >> 4) * 16));
                ldsm4(af, aoff);
                #pragma unroll
                for (int jp = 0; jp < 4; jp++) {
                    mma16816h(acc[mt][2*jp],   af, bf[jp][0], bf[jp][1]);
                    mma16816h(acc[mt][2*jp+1], af, bf[jp][2], bf[jp][3]);
                }
            }
        }
    }

    int g = lane >> 2, t2 = (lane & 3) * 2;
    const __half2 qsc = __float2half2_rn(QSCALE);
    #pragma unroll
    for (int mt = 0; mt < 4; mt++) {
        int row0 = crow + wm * 64 + mt * 16 + g;
        #pragma unroll
        for (int j = 0; j < 8; j++) {
            int col = ccol + wn * 64 + j * 8 + t2;
            int which = col >> 10, rem = col & 1023;
            int h = rem >> 6, d = rem & 63;
            __half* dst = (which == 0) ? g_q : (which == 1) ? g_k : g_v;
            #pragma unroll
            for (int r = 0; r < 2; r++) {
                int tok = row0 + r * 8;
                __half2 hv = *(__half2*)&acc[mt][j][r];
                if (which == 0) hv = __hmul2(hv, qsc);
                size_t off = ((size_t)((tok >> 11) * HEADS + h) * NSEQ +
                              (tok & (NSEQ - 1))) * HD + d;
                *(__half2*)(dst + off) = hv;
            }
        }
    }
}

// ---------------------------------------------------------------------------
// Proj GEMM: CTA 64x128 (M=64, N=128), 4 warps (warp 32x64), K-chunk 64,
// 2-stage, 4 CTAs/SM. Grid 512 -> balanced waves. +bias +residual, fp32 out.
// Stage 24KB: A@0 (8KB, 64 rows), B@8192 (16KB, 128 rows).
// ---------------------------------------------------------------------------
#define PSTAGE 24576
#define PSMEM  (2 * PSTAGE)

__device__ __forceinline__ void proj_load_stage(
    const __half* A, const __half* B, int crow, int ccol, int ch,
    uint32_t sbase, int tid) {
    #pragma unroll
    for (int j = 0; j < 4; j++) {             // A: 64 rows x 8 chunks = 512
        int i = tid + j * 128;
        int row = i >> 3, c16 = i & 7;
        uint32_t d = sbase + sw((uint32_t)(row * 128 + c16 * 16));
        CP16(d, A + (size_t)(crow + row) * DIM + ch * 64 + c16 * 8);
    }
    #pragma unroll
    for (int j = 0; j < 8; j++) {             // B: 128 rows x 8 chunks = 1024
        int i = tid + j * 128;
        int row = i >> 3, c16 = i & 7;
        uint32_t d = sbase + 8192 + sw((uint32_t)(row * 128 + c16 * 16));
        CP16(d, B + (size_t)(ccol + row) * DIM + ch * 64 + c16 * 8);
    }
}

__global__ __launch_bounds__(128, 4) void gemm_proj(
    const __half* __restrict__ A, const __half* __restrict__ B,
    float* __restrict__ out, const float* __restrict__ bias,
    const float* __restrict__ resid) {

    extern __shared__ char smc[];
    uint32_t smb = smem_u32(smc);
    int tid = threadIdx.x, wid = tid >> 5, lane = tid & 31;
    int wm = wid & 1, wn = wid >> 1;
    int crow = blockIdx.y * 64, ccol = blockIdx.x * 128;

    uint32_t acc[2][8][2];   // warp 32x64, fp16x2 acc
    #pragma unroll
    for (int a = 0; a < 2; a++)
        #pragma unroll
        for (int b = 0; b < 8; b++) { acc[a][b][0] = 0u; acc[a][b][1] = 0u; }

    proj_load_stage(A, B, crow, ccol, 0, smb, tid);
    CP_COMMIT();

    for (int ch = 0; ch < NCH; ch++) {
        CP_WAIT0();
        __syncthreads();
        if (ch + 1 < NCH) {
            proj_load_stage(A, B, crow, ccol, ch + 1,
                            smb + ((ch + 1) & 1) * PSTAGE, tid);
            CP_COMMIT();
        }

        uint32_t Abase = smb + (ch & 1) * PSTAGE;
        uint32_t Bbase = Abase + 8192;

        #pragma unroll
        for (int kt = 0; kt < 4; kt++) {
            uint32_t bf[4][4];
            #pragma unroll
            for (int jp = 0; jp < 4; jp++) {
                uint32_t boff = Bbase + sw((uint32_t)(
                    (wn * 64 + jp * 16 + (lane >> 4) * 8 + (lane & 7)) * 128 +
                    kt * 32 + ((lane >> 3) & 1) * 16));
                ldsm4(bf[jp], boff);
            }
            #pragma unroll
            for (int mt = 0; mt < 2; mt++) {
                uint32_t af[4];
                uint32_t aoff = Abase + sw((uint32_t)(
                    (wm * 32 + mt * 16 + (lane & 15)) * 128 +
                    kt * 32 + (lane >> 4) * 16));
                ldsm4(af, aoff);
                #pragma unroll
                for (int jp = 0; jp < 4; jp++) {
                    mma16816h(acc[mt][2*jp],   af, bf[jp][0], bf[jp][1]);
                    mma16816h(acc[mt][2*jp+1], af, bf[jp][2], bf[jp][3]);
                }
            }
        }
    }

    int g = lane >> 2, t2 = (lane & 3) * 2;
    #pragma unroll
    for (int mt = 0; mt < 2; mt++) {
        int row0 = crow + wm * 32 + mt * 16 + g;
        #pragma unroll
        for (int j = 0; j < 8; j++) {
            int col = ccol + wn * 64 + j * 8 + t2;
            float b0 = bias[col], b1 = bias[col + 1];
            #pragma unroll
            for (int r = 0; r < 2; r++) {
                size_t o = (size_t)(row0 + r * 8) * DIM + col;
                float2 rr = *(const float2*)(resid + o);
                float2 f = __half22float2(*(__half2*)&acc[mt][j][r]);
                float2 vv = { f.x + b0 + rr.x, f.y + b1 + rr.y };
                *(float2*)(out + o) = vv;
            }
        }
    }
}

// ---------------------------------------------------------------------------
// Flash attention, max-free (round-13 winner): CTA = 256 q x one (b,h),
// 4 warps x 64 q, full fp16 acc, P in place. 2 CTAs/SM.
// ---------------------------------------------------------------------------
#define ASTAGE 16384
#define ASMEM  (32768 + 3 * ASTAGE)
#define NT     (NSEQ / 64)   // 32

__device__ __forceinline__ void kv_load_stage(
    const __half* kg, const __half* vg, int k0, uint32_t sbase, int tid) {
    #pragma unroll
    for (int j = 0; j < 4; j++) {
        int i = tid + j * 128;
        int key = i >> 3, ck = i & 7;
        uint32_t d = sbase + sw((uint32_t)(key * 128 + ck * 16));
        size_t gsrc = (size_t)(k0 + key) * HD + ck * 8;
        CP16(d,        kg + gsrc);
        CP16(d + 8192, vg + gsrc);
    }
}

__global__ __launch_bounds__(128, 2) void attn_mma() {
    extern __shared__ char smc[];
    uint32_t smb = smem_u32(smc);
    int tid = threadIdx.x, wid = tid >> 5, lane = tid & 31;
    int bh = blockIdx.y;
    int q0 = blockIdx.x * 256;

    const __half* qg = g_q + (size_t)bh * NSEQ * HD;
    const __half* kg = g_k + (size_t)bh * NSEQ * HD;
    const __half* vg = g_v + (size_t)bh * NSEQ * HD;

    kv_load_stage(kg, vg, 0, smb + 32768, tid);
    CP_COMMIT();
    kv_load_stage(kg, vg, 64, smb + 32768 + ASTAGE, tid);
    CP_COMMIT();

    #pragma unroll
    for (int it = 0; it < 16; it++) {
        int i = tid + it * 128;
        int row = i >> 3, ck = i & 7;
        uint4 val = *(const uint4*)(qg + (size_t)(q0 + row) * HD + ck * 8);
        *(uint4*)(smc + sw((uint32_t)(row * 128 + ck * 16))) = val;
    }
    __syncthreads();

    uint32_t qa[4][4][4];
    #pragma unroll
    for (int mt = 0; mt < 4; mt++)
        #pragma unroll
        for (int kt = 0; kt < 4; kt++) {
            uint32_t off = smb + sw((uint32_t)(
                (wid * 64 + mt * 16 + (lane & 15)) * 128 +
                kt * 32 + (lane >> 4) * 16));
            ldsm4(qa[mt][kt], off);
        }

    uint32_t oh[4][8][2];
    #pragma unroll
    for (int mt = 0; mt < 4; mt++)
        #pragma unroll
        for (int j = 0; j < 8; j++) { oh[mt][j][0] = 0u; oh[mt][j][1] = 0u; }
    float l[4][2];
    #pragma unroll
    for (int mt = 0; mt < 4; mt++) { l[mt][0] = 0.f; l[mt][1] = 0.f; }

    for (int t = 0; t < NT; t++) {
        if (t + 2 < NT) CP_WAIT1(); else CP_WAIT0();
        __syncthreads();
        if (t + 2 < NT) {
            kv_load_stage(kg, vg, (t + 2) * 64,
                          smb + 32768 + ((t + 2) % 3) * ASTAGE, tid);
            CP_COMMIT();
        }

        uint32_t Kb = smb + 32768 + (t % 3) * ASTAGE;
        uint32_t Vb = Kb + 8192;

        uint32_t sc[4][8][2];
        #pragma unroll
        for (int mt = 0; mt < 4; mt++)
            #pragma unroll
            for (int j = 0; j < 8; j++) { sc[mt][j][0] = 0u; sc[mt][j][1] = 0u; }

        #pragma unroll
        for (int kt = 0; kt < 4; kt++) {
            uint32_t kf[4][4];
            #pragma unroll
            for (int jp = 0; jp < 4; jp++) {
                uint32_t off = Kb + sw((uint32_t)(
                    (jp * 16 + (lane >> 4) * 8 + (lane & 7)) * 128 +
                    kt * 32 + ((lane >> 3) & 1) * 16));
                ldsm4(kf[jp], off);
            }
            #pragma unroll
            for (int mt = 0; mt < 4; mt++)
                #pragma unroll
                for (int jp = 0; jp < 4; jp++) {
                    mma16816h(sc[mt][2*jp],   qa[mt][kt], kf[jp][0], kf[jp][1]);
                    mma16816h(sc[mt][2*jp+1], qa[mt][kt], kf[jp][2], kf[jp][3]);
                }
        }

        #pragma unroll
        for (int mt = 0; mt < 4; mt++) {
            __half2 ls0 = __float2half2_rn(0.f), ls1 = __float2half2_rn(0.f);
            #pragma unroll
            for (int j = 0; j < 8; j++) {
                sc[mt][j][0] = hex2(sc[mt][j][0]);
                sc[mt][j][1] = hex2(sc[mt][j][1]);
                ls0 = __hadd2(ls0, *(__half2*)&sc[mt][j][0]);
                ls1 = __hadd2(ls1, *(__half2*)&sc[mt][j][1]);
            }
            l[mt][0] += __low2float(ls0) + __high2float(ls0);
            l[mt][1] += __low2float(ls1) + __high2float(ls1);
        }

        #pragma unroll
        for (int kt = 0; kt < 4; kt++) {
            uint32_t vf[4][4];
            #pragma unroll
            for (int j2 = 0; j2 < 4; j2++) {
                uint32_t off = Vb + sw((uint32_t)(
                    (kt * 16 + ((lane >> 3) & 1) * 8 + (lane & 7)) * 128 +
                    j2 * 32 + ((lane >> 4) & 1) * 16));
                ldsm4t(vf[j2], off);
            }
            #pragma unroll
            for (int mt = 0; mt < 4; mt++)
                #pragma unroll
                for (int j2 = 0; j2 < 4; j2++) {
                    mma16816h(oh[mt][2*j2],   &sc[mt][2*kt][0], vf[j2][0], vf[j2][1]);
                    mma16816h(oh[mt][2*j2+1], &sc[mt][2*kt][0], vf[j2][2], vf[j2][3]);
                }
        }
    }

    int b = bh >> 4, h = bh & 15;
    #pragma unroll
    for (int mt = 0; mt < 4; mt++) {
        float l0 = l[mt][0], l1 = l[mt][1];
        l0 += __shfl_xor_sync(0xFFFFFFFFu, l0, 1);
        l0 += __shfl_xor_sync(0xFFFFFFFFu, l0, 2);
        l1 += __shfl_xor_sync(0xFFFFFFFFu, l1, 1);
        l1 += __shfl_xor_sync(0xFFFFFFFFu, l1, 2);
        float inv0 = 1.f / l0, inv1 = 1.f / l1;

        int n0 = q0 + wid * 64 + mt * 16 + (lane >> 2);
        size_t t0 = (size_t)(b * NSEQ + n0) * DIM + h * HD;
        size_t t1 = t0 + (size_t)8 * DIM;
        #pragma unroll
        for (int j = 0; j < 8; j++) {
            int d = j * 8 + (lane & 3) * 2;
            float2 f0 = __half22float2(*(__half2*)&oh[mt][j][0]);
            float2 f1 = __half22float2(*(__half2*)&oh[mt][j][1]);
            *(uint32_t*)(g_attn + t0 + d) = pack_f16(f0.x * inv0, f0.y * inv0);
            *(uint32_t*)(g_attn + t1 + d) = pack_f16(f1.x * inv1, f1.y * inv1);
        }
    }
}

// ---------------------------------------------------------------------------
extern "C" void kernel_launch(void* const* d_in, const int* in_sizes, int n_in,
                              void* d_out, int out_size) {
    const float* x      = (const float*)d_in[0];
    const float* w_qkv  = (const float*)d_in[1];
    const float* w_proj = (const float*)d_in[2];
    const float* b_proj = (const float*)d_in[3];
    const float* gamma  = (const float*)d_in[4];
    const float* beta   = (const float*)d_in[5];
    float* out = (float*)d_out;

    cudaFuncSetAttribute(gemm_qkv,  cudaFuncAttributeMaxDynamicSharedMemorySize, GSMEM);
    cudaFuncSetAttribute(gemm_proj, cudaFuncAttributeMaxDynamicSharedMemorySize, PSMEM);
    cudaFuncSetAttribute(attn_mma,  cudaFuncAttributeMaxDynamicSharedMemorySize, ASMEM);

    __half *lnp, *wqp, *wpp, *atp;
    cudaGetSymbolAddress((void**)&lnp, g_ln);
    cudaGetSymbolAddress((void**)&wqp, g_wqkvT);
    cudaGetSymbolAddress((void**)&wpp, g_wprojT);
    cudaGetSymbolAddress((void**)&atp, g_attn);

    // 1. merged pre-pass: LN + both weight transposes
    prepass_kernel<<<PREPASS_BLOCKS, 256>>>(x, gamma, beta, w_qkv, w_proj);

    // 2. QKV GEMM (128x128) -> scatter fp16 q/k/v
    gemm_qkv<<<dim3(C3 / 128, TOKENS / 128), 128, GSMEM>>>(lnp, wqp);

    // 3. attention (256-q CTAs) -> fp16 [token][1024]
    attn_mma<<<dim3(NSEQ / 256, BATCH * HEADS), 128, ASMEM>>>();

    // 4. proj GEMM (64x128 tiles, grid 512) + bias + residual -> d_out
    gemm_proj<<<dim3(DIM / 128, TOKENS / 64), 128, PSMEM>>>(
        atp, wpp, out, b_proj, x);
}

// round 16
// speedup vs baseline: 1.0836x; 1.0272x over previous
#include <cuda_runtime.h>
#include <cuda_fp16.h>
#include <math.h>
#include <stdint.h>

#define DIM    1024
#define BATCH  2
#define NSEQ   2048
#define HEADS  16
#define HD     64
#define TOKENS (BATCH * NSEQ)     // 4096
#define C3     (3 * DIM)          // 3072
#define QSCALE 0.1803368801111204f   // 0.125 * log2(e)

// ---------------- scratch -----------------------------------------------
__device__ __half g_ln[TOKENS * DIM];
__device__ __half g_wqkvT[C3 * DIM];    // [N=3072][K=1024]
__device__ __half g_wprojT[DIM * DIM];  // [N=1024][K=1024]
__device__ __half g_q[BATCH * HEADS * NSEQ * HD];   // [bh][n][64], pre-scaled
__device__ __half g_k[BATCH * HEADS * NSEQ * HD];
__device__ __half g_v[BATCH * HEADS * NSEQ * HD];
__device__ __half g_attn[TOKENS * DIM];

// ---------------- helpers ------------------------------------------------
__device__ __forceinline__ uint32_t smem_u32(const void* p) {
    uint32_t a;
    asm("{ .reg .u64 t; cvta.to.shared.u64 t, %1; cvt.u32.u64 %0, t; }"
        : "=r"(a) : "l"(p));
    return a;
}
__device__ __forceinline__ uint32_t sw(uint32_t o) {   // SW128 XOR swizzle
    return o ^ ((o >> 3) & 0x70);
}
__device__ __forceinline__ void ldsm4(uint32_t* r, uint32_t a) {
    asm volatile("ldmatrix.sync.aligned.m8n8.x4.shared.b16 {%0,%1,%2,%3}, [%4];"
                 : "=r"(r[0]), "=r"(r[1]), "=r"(r[2]), "=r"(r[3]) : "r"(a));
}
__device__ __forceinline__ void ldsm4t(uint32_t* r, uint32_t a) {
    asm volatile("ldmatrix.sync.aligned.m8n8.x4.trans.shared.b16 {%0,%1,%2,%3}, [%4];"
                 : "=r"(r[0]), "=r"(r[1]), "=r"(r[2]), "=r"(r[3]) : "r"(a));
}
// fp16-acc MMA
__device__ __forceinline__ void mma16816h(uint32_t* c, const uint32_t* a,
                                          uint32_t b0, uint32_t b1) {
    asm volatile(
        "mma.sync.aligned.m16n8k16.row.col.f16.f16.f16.f16 "
        "{%0,%1}, {%2,%3,%4,%5}, {%6,%7}, {%0,%1};"
        : "+r"(c[0]), "+r"(c[1])
        : "r"(a[0]), "r"(a[1]), "r"(a[2]), "r"(a[3]), "r"(b0), "r"(b1));
}
#define CP16(dst, src) \
    asm volatile("cp.async.cg.shared.global [%0], [%1], 16;" :: "r"(dst), "l"(src))
#define CP_COMMIT() asm volatile("cp.async.commit_group;" ::: "memory")
#define CP_WAIT1()  asm volatile("cp.async.wait_group 1;" ::: "memory")
#define CP_WAIT0()  asm volatile("cp.async.wait_group 0;" ::: "memory")

__device__ __forceinline__ uint32_t hex2(uint32_t x) {   // 2^x on fp16x2
    uint32_t y;
    asm("ex2.approx.f16x2 %0, %1;" : "=r"(y) : "r"(x));
    return y;
}
__device__ __forceinline__ uint32_t pack_f16(float lo, float hi) {
    uint32_t r;
    asm("cvt.rn.f16x2.f32 %0, %1, %2;" : "=r"(r) : "f"(hi), "f"(lo));
    return r;
}

// ---------------------------------------------------------------------------
// Merged pre-pass: LN rows (blocks 0..4095) + wqkv transpose + wproj transpose.
// ---------------------------------------------------------------------------
__device__ __forceinline__ void do_transpose(
    const float* __restrict__ W, __half* __restrict__ T,
    int K, int N, int n0, int k0, int tid) {
    __shared__ float tile[32][33];
    int tx = tid & 31, ty = tid >> 5;
    #pragma unroll
    for (int r = ty; r < 32; r += 8)
        tile[r][tx] = W[(size_t)(k0 + r) * N + n0 + tx];
    __syncthreads();
    #pragma unroll
    for (int r = ty; r < 32; r += 8)
        T[(size_t)(n0 + r) * K + k0 + tx] = __float2half(tile[tx][r]);
}

__global__ __launch_bounds__(256) void prepass_kernel(
    const float* __restrict__ x, const float* __restrict__ gamma,
    const float* __restrict__ beta, const float* __restrict__ w_qkv,
    const float* __restrict__ w_proj) {
    int bx = blockIdx.x;
    int t = threadIdx.x;

    if (bx < TOKENS) {
        int row = bx;
        const float4* xr = (const float4*)(x + (size_t)row * DIM);
        float4 v = xr[t];

        float s  = v.x + v.y + v.z + v.w;
        float ss = v.x*v.x + v.y*v.y + v.z*v.z + v.w*v.w;
        #pragma unroll
        for (int o = 16; o > 0; o >>= 1) {
            s  += __shfl_xor_sync(0xFFFFFFFFu, s,  o);
            ss += __shfl_xor_sync(0xFFFFFFFFu, ss, o);
        }
        __shared__ float rs[8], rss[8];
        int w = t >> 5;
        if ((t & 31) == 0) { rs[w] = s; rss[w] = ss; }
        __syncthreads();
        s = 0.f; ss = 0.f;
        #pragma unroll
        for (int i = 0; i < 8; i++) { s += rs[i]; ss += rss[i]; }

        const float invD = 1.0f / DIM;
        float mean = s * invD;
        float var  = ss * invD - mean * mean;
        float rstd = rsqrtf(var + 1e-5f);

        float4 g  = ((const float4*)gamma)[t];
        float4 be = ((const float4*)beta)[t];
        float o0 = (v.x - mean) * rstd * g.x + be.x;
        float o1 = (v.y - mean) * rstd * g.y + be.y;
        float o2 = (v.z - mean) * rstd * g.z + be.z;
        float o3 = (v.w - mean) * rstd * g.w + be.w;

        size_t idx = (size_t)row * DIM + t * 4;
        *(uint32_t*)(g_ln + idx)     = pack_f16(o0, o1);
        *(uint32_t*)(g_ln + idx + 2) = pack_f16(o2, o3);
    } else if (bx < TOKENS + (C3 / 32) * (DIM / 32)) {
        int id = bx - TOKENS;
        int n0 = (id % (C3 / 32)) * 32;
        int k0 = (id / (C3 / 32)) * 32;
        do_transpose(w_qkv, g_wqkvT, DIM, C3, n0, k0, t);
    } else {
        int id = bx - TOKENS - (C3 / 32) * (DIM / 32);
        int n0 = (id % (DIM / 32)) * 32;
        int k0 = (id / (DIM / 32)) * 32;
        do_transpose(w_proj, g_wprojT, DIM, DIM, n0, k0, t);
    }
}
#define PREPASS_BLOCKS (TOKENS + (C3 / 32) * (DIM / 32) + (DIM / 32) * (DIM / 32))

// ---------------------------------------------------------------------------
// QKV GEMM: CTA 128x128, 4 warps (2x2, warp 64x64), K-chunk 64, 2-stage
// cp.async, 3 CTAs/SM. NEW: epilogue staged through smem -> coalesced uint4
// stores to q/k/v (replaces scattered half2 stores).
// ---------------------------------------------------------------------------
#define GSTAGE 32768
#define GSMEM  (2 * GSTAGE)
#define NCH    (DIM / 64)   // 16

__device__ __forceinline__ void gemm_load_stage(
    const __half* A, const __half* B, int crow, int ccol, int ch,
    uint32_t sbase, int tid) {
    #pragma unroll
    for (int j = 0; j < 8; j++) {
        int i = tid + j * 128;
        int row = i >> 3, c16 = i & 7;
        uint32_t d = sbase + sw((uint32_t)(row * 128 + c16 * 16));
        size_t off = (size_t)row * DIM + ch * 64 + c16 * 8;
        CP16(d,         A + (size_t)crow * DIM + off);
        CP16(d + 16384, B + (size_t)ccol * DIM + off);
    }
}

__global__ __launch_bounds__(128, 3) void gemm_qkv(
    const __half* __restrict__ A, const __half* __restrict__ B) {

    extern __shared__ char smc[];
    uint32_t smb = smem_u32(smc);
    int tid = threadIdx.x, wid = tid >> 5, lane = tid & 31;
    int wm = wid & 1, wn = wid >> 1;
    int crow = blockIdx.y * 128, ccol = blockIdx.x * 128;

    uint32_t acc[4][8][2];
    #pragma unroll
    for (int a = 0; a < 4; a++)
        #pragma unroll
        for (int b = 0; b < 8; b++) { acc[a][b][0] = 0u; acc[a][b][1] = 0u; }

    gemm_load_stage(A, B, crow, ccol, 0, smb, tid);
    CP_COMMIT();

    for (int ch = 0; ch < NCH; ch++) {
        CP_WAIT0();
        __syncthreads();
        if (ch + 1 < NCH) {
            gemm_load_stage(A, B, crow, ccol, ch + 1,
                            smb + ((ch + 1) & 1) * GSTAGE, tid);
            CP_COMMIT();
        }

        uint32_t Abase = smb + (ch & 1) * GSTAGE;
        uint32_t Bbase = Abase + 16384;

        #pragma unroll
        for (int kt = 0; kt < 4; kt++) {
            uint32_t bf[4][4];
            #pragma unroll
            for (int jp = 0; jp < 4; jp++) {
                uint32_t boff = Bbase + sw((uint32_t)(
                    (wn * 64 + jp * 16 + (lane >> 4) * 8 + (lane & 7)) * 128 +
                    kt * 32 + ((lane >> 3) & 1) * 16));
                ldsm4(bf[jp], boff);
            }
            #pragma unroll
            for (int mt = 0; mt < 4; mt++) {
                uint32_t af[4];
                uint32_t aoff = Abase + sw((uint32_t)(
                    (wm * 64 + mt * 16 + (lane & 15)) * 128 +
                    kt * 32 + (lane >> 4) * 16));
                ldsm4(af, aoff);
                #pragma unroll
                for (int jp = 0; jp < 4; jp++) {
                    mma16816h(acc[mt][2*jp],   af, bf[jp][0], bf[jp][1]);
                    mma16816h(acc[mt][2*jp+1], af, bf[jp][2], bf[jp][3]);
                }
            }
        }
    }

    // ---- epilogue: stage 128x128 fp16 tile in smem (256B rows, row-swizzled)
    __syncthreads();
    int g = lane >> 2, t2 = (lane & 3) * 2;
    #pragma unroll
    for (int mt = 0; mt < 4; mt++) {
        #pragma unroll
        for (int j = 0; j < 8; j++) {
            int colL = wn * 64 + j * 8 + t2;
            #pragma unroll
            for (int r = 0; r < 2; r++) {
                int rowL = wm * 64 + mt * 16 + g + r * 8;
                *(uint32_t*)(smc + sw((uint32_t)(rowL * 256 + colL * 2))) =
                    acc[mt][j][r];
            }
        }
    }
    __syncthreads();

    // coalesced read-out: 2048 uint4 chunks (128 toks x 2 heads x 8 chunks)
    int which = ccol >> 10;                 // 0=Q 1=K 2=V (constant per CTA)
    int hbase = (ccol & 1023) >> 6;         // first head in this CTA
    __half* dst = (which == 0) ? g_q : (which == 1) ? g_k : g_v;
    const __half2 qsc = __float2half2_rn(QSCALE);

    #pragma unroll
    for (int k = 0; k < 16; k++) {
        int i = tid + k * 128;
        int tokL = i >> 4, head = (i >> 3) & 1, ck = i & 7;
        uint4 v = *(uint4*)(smc + sw((uint32_t)(tokL * 256 + head * 128 + ck * 16)));
        if (which == 0) {
            __half2* h2 = (__half2*)&v;
            h2[0] = __hmul2(h2[0], qsc); h2[1] = __hmul2(h2[1], qsc);
            h2[2] = __hmul2(h2[2], qsc); h2[3] = __hmul2(h2[3], qsc);
        }
        int tok = crow + tokL;
        int h = hbase + head;
        size_t off = ((size_t)((tok >> 11) * HEADS + h) * NSEQ +
                      (tok & (NSEQ - 1))) * HD + ck * 8;
        *(uint4*)(dst + off) = v;
    }
}

// ---------------------------------------------------------------------------
// Proj GEMM (round-15): CTA 64x128, 4 warps (warp 32x64), K-chunk 64,
// 2-stage, 4 CTAs/SM, grid 512. +bias +residual, fp32 out.
// ---------------------------------------------------------------------------
#define PSTAGE 24576
#define PSMEM  (2 * PSTAGE)

__device__ __forceinline__ void proj_load_stage(
    const __half* A, const __half* B, int crow, int ccol, int ch,
    uint32_t sbase, int tid) {
    #pragma unroll
    for (int j = 0; j < 4; j++) {
        int i = tid + j * 128;
        int row = i >> 3, c16 = i & 7;
        uint32_t d = sbase + sw((uint32_t)(row * 128 + c16 * 16));
        CP16(d, A + (size_t)(crow + row) * DIM + ch * 64 + c16 * 8);
    }
    #pragma unroll
    for (int j = 0; j < 8; j++) {
        int i = tid + j * 128;
        int row = i >> 3, c16 = i & 7;
        uint32_t d = sbase + 8192 + sw((uint32_t)(row * 128 + c16 * 16));
        CP16(d, B + (size_t)(ccol + row) * DIM + ch * 64 + c16 * 8);
    }
}

__global__ __launch_bounds__(128, 4) void gemm_proj(
    const __half* __restrict__ A, const __half* __restrict__ B,
    float* __restrict__ out, const float* __restrict__ bias,
    const float* __restrict__ resid) {

    extern __shared__ char smc[];
    uint32_t smb = smem_u32(smc);
    int tid = threadIdx.x, wid = tid >> 5, lane = tid & 31;
    int wm = wid & 1, wn = wid >> 1;
    int crow = blockIdx.y * 64, ccol = blockIdx.x * 128;

    uint32_t acc[2][8][2];
    #pragma unroll
    for (int a = 0; a < 2; a++)
        #pragma unroll
        for (int b = 0; b < 8; b++) { acc[a][b][0] = 0u; acc[a][b][1] = 0u; }

    proj_load_stage(A, B, crow, ccol, 0, smb, tid);
    CP_COMMIT();

    for (int ch = 0; ch < NCH; ch++) {
        CP_WAIT0();
        __syncthreads();
        if (ch + 1 < NCH) {
            proj_load_stage(A, B, crow, ccol, ch + 1,
                            smb + ((ch + 1) & 1) * PSTAGE, tid);
            CP_COMMIT();
        }

        uint32_t Abase = smb + (ch & 1) * PSTAGE;
        uint32_t Bbase = Abase + 8192;

        #pragma unroll
        for (int kt = 0; kt < 4; kt++) {
            uint32_t bf[4][4];
            #pragma unroll
            for (int jp = 0; jp < 4; jp++) {
                uint32_t boff = Bbase + sw((uint32_t)(
                    (wn * 64 + jp * 16 + (lane >> 4) * 8 + (lane & 7)) * 128 +
                    kt * 32 + ((lane >> 3) & 1) * 16));
                ldsm4(bf[jp], boff);
            }
            #pragma unroll
            for (int mt = 0; mt < 2; mt++) {
                uint32_t af[4];
                uint32_t aoff = Abase + sw((uint32_t)(
                    (wm * 32 + mt * 16 + (lane & 15)) * 128 +
                    kt * 32 + (lane >> 4) * 16));
                ldsm4(af, aoff);
                #pragma unroll
                for (int jp = 0; jp < 4; jp++) {
                    mma16816h(acc[mt][2*jp],   af, bf[jp][0], bf[jp][1]);
                    mma16816h(acc[mt][2*jp+1], af, bf[jp][2], bf[jp][3]);
                }
            }
        }
    }

    int g = lane >> 2, t2 = (lane & 3) * 2;
    #pragma unroll
    for (int mt = 0; mt < 2; mt++) {
        int row0 = crow + wm * 32 + mt * 16 + g;
        #pragma unroll
        for (int j = 0; j < 8; j++) {
            int col = ccol + wn * 64 + j * 8 + t2;
            float b0 = bias[col], b1 = bias[col + 1];
            #pragma unroll
            for (int r = 0; r < 2; r++) {
                size_t o = (size_t)(row0 + r * 8) * DIM + col;
                float2 rr = *(const float2*)(resid + o);
                float2 f = __half22float2(*(__half2*)&acc[mt][j][r]);
                float2 vv = { f.x + b0 + rr.x, f.y + b1 + rr.y };
                *(float2*)(out + o) = vv;
            }
        }
    }
}

// ---------------------------------------------------------------------------
// Flash attention, max-free (round-13 winner): CTA = 256 q x one (b,h),
// 4 warps x 64 q, full fp16 acc, P in place. 2 CTAs/SM.
// ---------------------------------------------------------------------------
#define ASTAGE 16384
#define ASMEM  (32768 + 3 * ASTAGE)
#define NT     (NSEQ / 64)   // 32

__device__ __forceinline__ void kv_load_stage(
    const __half* kg, const __half* vg, int k0, uint32_t sbase, int tid) {
    #pragma unroll
    for (int j = 0; j < 4; j++) {
        int i = tid + j * 128;
        int key = i >> 3, ck = i & 7;
        uint32_t d = sbase + sw((uint32_t)(key * 128 + ck * 16));
        size_t gsrc = (size_t)(k0 + key) * HD + ck * 8;
        CP16(d,        kg + gsrc);
        CP16(d + 8192, vg + gsrc);
    }
}

__global__ __launch_bounds__(128, 2) void attn_mma() {
    extern __shared__ char smc[];
    uint32_t smb = smem_u32(smc);
    int tid = threadIdx.x, wid = tid >> 5, lane = tid & 31;
    int bh = blockIdx.y;
    int q0 = blockIdx.x * 256;

    const __half* qg = g_q + (size_t)bh * NSEQ * HD;
    const __half* kg = g_k + (size_t)bh * NSEQ * HD;
    const __half* vg = g_v + (size_t)bh * NSEQ * HD;

    kv_load_stage(kg, vg, 0, smb + 32768, tid);
    CP_COMMIT();
    kv_load_stage(kg, vg, 64, smb + 32768 + ASTAGE, tid);
    CP_COMMIT();

    #pragma unroll
    for (int it = 0; it < 16; it++) {
        int i = tid + it * 128;
        int row = i >> 3, ck = i & 7;
        uint4 val = *(const uint4*)(qg + (size_t)(q0 + row) * HD + ck * 8);
        *(uint4*)(smc + sw((uint32_t)(row * 128 + ck * 16))) = val;
    }
    __syncthreads();

    uint32_t qa[4][4][4];
    #pragma unroll
    for (int mt = 0; mt < 4; mt++)
        #pragma unroll
        for (int kt = 0; kt < 4; kt++) {
            uint32_t off = smb + sw((uint32_t)(
                (wid * 64 + mt * 16 + (lane & 15)) * 128 +
                kt * 32 + (lane >> 4) * 16));
            ldsm4(qa[mt][kt], off);
        }

    uint32_t oh[4][8][2];
    #pragma unroll
    for (int mt = 0; mt < 4; mt++)
        #pragma unroll
        for (int j = 0; j < 8; j++) { oh[mt][j][0] = 0u; oh[mt][j][1] = 0u; }
    float l[4][2];
    #pragma unroll
    for (int mt = 0; mt < 4; mt++) { l[mt][0] = 0.f; l[mt][1] = 0.f; }

    for (int t = 0; t < NT; t++) {
        if (t + 2 < NT) CP_WAIT1(); else CP_WAIT0();
        __syncthreads();
        if (t + 2 < NT) {
            kv_load_stage(kg, vg, (t + 2) * 64,
                          smb + 32768 + ((t + 2) % 3) * ASTAGE, tid);
            CP_COMMIT();
        }

        uint32_t Kb = smb + 32768 + (t % 3) * ASTAGE;
        uint32_t Vb = Kb + 8192;

        uint32_t sc[4][8][2];
        #pragma unroll
        for (int mt = 0; mt < 4; mt++)
            #pragma unroll
            for (int j = 0; j < 8; j++) { sc[mt][j][0] = 0u; sc[mt][j][1] = 0u; }

        #pragma unroll
        for (int kt = 0; kt < 4; kt++) {
            uint32_t kf[4][4];
            #pragma unroll
            for (int jp = 0; jp < 4; jp++) {
                uint32_t off = Kb + sw((uint32_t)(
                    (jp * 16 + (lane >> 4) * 8 + (lane & 7)) * 128 +
                    kt * 32 + ((lane >> 3) & 1) * 16));
                ldsm4(kf[jp], off);
            }
            #pragma unroll
            for (int mt = 0; mt < 4; mt++)
                #pragma unroll
                for (int jp = 0; jp < 4; jp++) {
                    mma16816h(sc[mt][2*jp],   qa[mt][kt], kf[jp][0], kf[jp][1]);
                    mma16816h(sc[mt][2*jp+1], qa[mt][kt], kf[jp][2], kf[jp][3]);
                }
        }

        #pragma unroll
        for (int mt = 0; mt < 4; mt++) {
            __half2 ls0 = __float2half2_rn(0.f), ls1 = __float2half2_rn(0.f);
            #pragma unroll
            for (int j = 0; j < 8; j++) {
                sc[mt][j][0] = hex2(sc[mt][j][0]);
                sc[mt][j][1] = hex2(sc[mt][j][1]);
                ls0 = __hadd2(ls0, *(__half2*)&sc[mt][j][0]);
                ls1 = __hadd2(ls1, *(__half2*)&sc[mt][j][1]);
            }
            l[mt][0] += __low2float(ls0) + __high2float(ls0);
            l[mt][1] += __low2float(ls1) + __high2float(ls1);
        }

        #pragma unroll
        for (int kt = 0; kt < 4; kt++) {
            uint32_t vf[4][4];
            #pragma unroll
            for (int j2 = 0; j2 < 4; j2++) {
                uint32_t off = Vb + sw((uint32_t)(
                    (kt * 16 + ((lane >> 3) & 1) * 8 + (lane & 7)) * 128 +
                    j2 * 32 + ((lane >> 4) & 1) * 16));
                ldsm4t(vf[j2], off);
            }
            #pragma unroll
            for (int mt = 0; mt < 4; mt++)
                #pragma unroll
                for (int j2 = 0; j2 < 4; j2++) {
                    mma16816h(oh[mt][2*j2],   &sc[mt][2*kt][0], vf[j2][0], vf[j2][1]);
                    mma16816h(oh[mt][2*j2+1], &sc[mt][2*kt][0], vf[j2][2], vf[j2][3]);
                }
        }
    }

    int b = bh >> 4, h = bh & 15;
    #pragma unroll
    for (int mt = 0; mt < 4; mt++) {
        float l0 = l[mt][0], l1 = l[mt][1];
        l0 += __shfl_xor_sync(0xFFFFFFFFu, l0, 1);
        l0 += __shfl_xor_sync(0xFFFFFFFFu, l0, 2);
        l1 += __shfl_xor_sync(0xFFFFFFFFu, l1, 1);
        l1 += __shfl_xor_sync(0xFFFFFFFFu, l1, 2);
        float inv0 = 1.f / l0, inv1 = 1.f / l1;

        int n0 = q0 + wid * 64 + mt * 16 + (lane >> 2);
        size_t t0 = (size_t)(b * NSEQ + n0) * DIM + h * HD;
        size_t t1 = t0 + (size_t)8 * DIM;
        #pragma unroll
        for (int j = 0; j < 8; j++) {
            int d = j * 8 + (lane & 3) * 2;
            float2 f0 = __half22float2(*(__half2*)&oh[mt][j][0]);
            float2 f1 = __half22float2(*(__half2*)&oh[mt][j][1]);
            *(uint32_t*)(g_attn + t0 + d) = pack_f16(f0.x * inv0, f0.y * inv0);
            *(uint32_t*)(g_attn + t1 + d) = pack_f16(f1.x * inv1, f1.y * inv1);
        }
    }
}

// ---------------------------------------------------------------------------
extern "C" void kernel_launch(void* const* d_in, const int* in_sizes, int n_in,
                              void* d_out, int out_size) {
    const float* x      = (const float*)d_in[0];
    const float* w_qkv  = (const float*)d_in[1];
    const float* w_proj = (const float*)d_in[2];
    const float* b_proj = (const float*)d_in[3];
    const float* gamma  = (const float*)d_in[4];
    const float* beta   = (const float*)d_in[5];
    float* out = (float*)d_out;

    cudaFuncSetAttribute(gemm_qkv,  cudaFuncAttributeMaxDynamicSharedMemorySize, GSMEM);
    cudaFuncSetAttribute(gemm_proj, cudaFuncAttributeMaxDynamicSharedMemorySize, PSMEM);
    cudaFuncSetAttribute(attn_mma,  cudaFuncAttributeMaxDynamicSharedMemorySize, ASMEM);

    __half *lnp, *wqp, *wpp, *atp;
    cudaGetSymbolAddress((void**)&lnp, g_ln);
    cudaGetSymbolAddress((void**)&wqp, g_wqkvT);
    cudaGetSymbolAddress((void**)&wpp, g_wprojT);
    cudaGetSymbolAddress((void**)&atp, g_attn);

    // 1. merged pre-pass: LN + both weight transposes
    prepass_kernel<<<PREPASS_BLOCKS, 256>>>(x, gamma, beta, w_qkv, w_proj);

    // 2. QKV GEMM (128x128, smem-staged coalesced epilogue)
    gemm_qkv<<<dim3(C3 / 128, TOKENS / 128), 128, GSMEM>>>(lnp, wqp);

    // 3. attention (256-q CTAs) -> fp16 [token][1024]
    attn_mma<<<dim3(NSEQ / 256, BATCH * HEADS), 128, ASMEM>>>();

    // 4. proj GEMM (64x128 tiles, grid 512) + bias + residual -> d_out
    gemm_proj<<<dim3(DIM / 128, TOKENS / 64), 128, PSMEM>>>(
        atp, wpp, out, b_proj, x);
}